// round 1
// baseline (speedup 1.0000x reference)
#include <cuda_runtime.h>
#include <cstdint>

#define L_SEQ 4096
#define DHEAD 128
#define QTILE 64
#define KTILE 64
#define NWARPS 4

// smem strides (in 32-bit words) chosen for conflict-free fragment access
#define KSTRIDE 132   // bank = 4*key + dim  -> distinct for B-frag pattern of S-mma
#define VSTRIDE 136   // bank = 8*key + dim  -> distinct for B-frag pattern of PV-mma
#define PSTRIDE 68    // bank = 4*row + col  -> distinct for A-frag pattern of PV-mma

#define SK_WORDS (KTILE * KSTRIDE)            // 8448
#define SV_WORDS (KTILE * VSTRIDE)            // 8704
#define SP_WORDS (16 * PSTRIDE)               // per warp: 1088
#define SMEM_WORDS (SK_WORDS + SV_WORDS + NWARPS * SP_WORDS)
#define SMEM_BYTES (SMEM_WORDS * 4)           // 86016

__device__ __forceinline__ uint32_t f2tf(float x) {
    uint32_t y;
    asm("cvt.rna.tf32.f32 %0, %1;" : "=r"(y) : "f"(x));
    return y;
}

__device__ __forceinline__ void mma_tf32(float c[4], const uint32_t a[4],
                                         uint32_t b0, uint32_t b1) {
    asm volatile(
        "mma.sync.aligned.m16n8k8.row.col.f32.tf32.tf32.f32 "
        "{%0,%1,%2,%3}, {%4,%5,%6,%7}, {%8,%9}, {%0,%1,%2,%3};\n"
        : "+f"(c[0]), "+f"(c[1]), "+f"(c[2]), "+f"(c[3])
        : "r"(a[0]), "r"(a[1]), "r"(a[2]), "r"(a[3]), "r"(b0), "r"(b1));
}

__global__ void __launch_bounds__(128, 1)
swa_kernel(const float* __restrict__ Q, const float* __restrict__ K,
           const float* __restrict__ V, float* __restrict__ O)
{
    extern __shared__ uint32_t smem[];
    uint32_t* sk = smem;                       // [KTILE][KSTRIDE] tf32
    uint32_t* sv = sk + SK_WORDS;              // [KTILE][VSTRIDE] tf32
    uint32_t* sp_all = sv + SV_WORDS;          // [NWARPS][16][PSTRIDE] tf32

    const int qt0  = blockIdx.x * QTILE;
    const int bh   = blockIdx.y;
    const size_t base = (size_t)bh * (L_SEQ * DHEAD);

    const int tid  = threadIdx.x;
    const int lane = tid & 31;
    const int warp = tid >> 5;
    const int g    = lane >> 2;   // groupID (row within 8)
    const int tg   = lane & 3;    // thread-in-group

    uint32_t* sp = sp_all + warp * SP_WORDS;

    const float scale = 0.08838834764831845f;  // 1/sqrt(128)

    // ---- Load Q fragments (tf32, pre-scaled), persistent in registers ----
    uint32_t aq[16][4];
    {
        const float* q0 = Q + base + (size_t)(qt0 + warp * 16 + g) * DHEAD;
        const float* q1 = q0 + 8 * DHEAD;
#pragma unroll
        for (int ks = 0; ks < 16; ks++) {
            aq[ks][0] = f2tf(q0[ks * 8 + tg] * scale);
            aq[ks][1] = f2tf(q1[ks * 8 + tg] * scale);
            aq[ks][2] = f2tf(q0[ks * 8 + tg + 4] * scale);
            aq[ks][3] = f2tf(q1[ks * 8 + tg + 4] * scale);
        }
    }

    // ---- Output accumulators + online-softmax state ----
    float oacc[16][4];
#pragma unroll
    for (int nb = 0; nb < 16; nb++) {
        oacc[nb][0] = 0.f; oacc[nb][1] = 0.f; oacc[nb][2] = 0.f; oacc[nb][3] = 0.f;
    }
    float m0 = -1e30f, m1 = -1e30f, l0 = 0.f, l1 = 0.f;

    const int blk    = qt0 >> 10;                 // 1024-query window block
    const int kstart = max(0, (blk << 10) - 512); // 512-aligned -> tile-aligned

    for (int kt = kstart; kt < qt0 + QTILE; kt += KTILE) {
        __syncthreads();   // all warps done reading previous K/V tile

        // ---- Stage K & V tiles into smem as tf32 (coalesced 512B rows) ----
#pragma unroll
        for (int it = 0; it < 16; it++) {
            int idx = tid + it * 128;           // float4 unit index, 0..2047
            int row = idx >> 5;
            int c4  = (idx & 31) << 2;
            const float4 k4 = *(const float4*)(K + base + (size_t)(kt + row) * DHEAD + c4);
            const float4 v4 = *(const float4*)(V + base + (size_t)(kt + row) * DHEAD + c4);
            uint4 kc, vc;
            kc.x = f2tf(k4.x); kc.y = f2tf(k4.y); kc.z = f2tf(k4.z); kc.w = f2tf(k4.w);
            vc.x = f2tf(v4.x); vc.y = f2tf(v4.y); vc.z = f2tf(v4.z); vc.w = f2tf(v4.w);
            *(uint4*)(sk + row * KSTRIDE + c4) = kc;
            *(uint4*)(sv + row * VSTRIDE + c4) = vc;
        }
        __syncthreads();

        // ---- S = Q * K^T  (16 queries x 64 keys per warp) ----
        float sacc[8][4];
#pragma unroll
        for (int nb = 0; nb < 8; nb++) {
            sacc[nb][0] = 0.f; sacc[nb][1] = 0.f; sacc[nb][2] = 0.f; sacc[nb][3] = 0.f;
        }
#pragma unroll
        for (int ks = 0; ks < 16; ks++) {
#pragma unroll
            for (int nb = 0; nb < 8; nb++) {
                uint32_t b0 = sk[(nb * 8 + g) * KSTRIDE + ks * 8 + tg];
                uint32_t b1 = sk[(nb * 8 + g) * KSTRIDE + ks * 8 + tg + 4];
                mma_tf32(sacc[nb], aq[ks], b0, b1);
            }
        }

        // ---- Causal mask (only the diagonal tile: kt == qt0) ----
        if (kt == qt0) {
            int r0 = warp * 16 + g;
            int r1 = r0 + 8;
#pragma unroll
            for (int nb = 0; nb < 8; nb++) {
                int c0 = nb * 8 + 2 * tg;
                int c1 = c0 + 1;
                if (c0 > r0) sacc[nb][0] = -1e30f;
                if (c1 > r0) sacc[nb][1] = -1e30f;
                if (c0 > r1) sacc[nb][2] = -1e30f;
                if (c1 > r1) sacc[nb][3] = -1e30f;
            }
        }

        // ---- Online softmax ----
        float tm0 = -1e30f, tm1 = -1e30f;
#pragma unroll
        for (int nb = 0; nb < 8; nb++) {
            tm0 = fmaxf(tm0, fmaxf(sacc[nb][0], sacc[nb][1]));
            tm1 = fmaxf(tm1, fmaxf(sacc[nb][2], sacc[nb][3]));
        }
        tm0 = fmaxf(tm0, __shfl_xor_sync(0xffffffffu, tm0, 1));
        tm0 = fmaxf(tm0, __shfl_xor_sync(0xffffffffu, tm0, 2));
        tm1 = fmaxf(tm1, __shfl_xor_sync(0xffffffffu, tm1, 1));
        tm1 = fmaxf(tm1, __shfl_xor_sync(0xffffffffu, tm1, 2));

        float mn0 = fmaxf(m0, tm0), mn1 = fmaxf(m1, tm1);
        float al0 = __expf(m0 - mn0), al1 = __expf(m1 - mn1);
        m0 = mn0; m1 = mn1;

        float rs0 = 0.f, rs1 = 0.f;
#pragma unroll
        for (int nb = 0; nb < 8; nb++) {
            float p00 = __expf(sacc[nb][0] - mn0);
            float p01 = __expf(sacc[nb][1] - mn0);
            float p10 = __expf(sacc[nb][2] - mn1);
            float p11 = __expf(sacc[nb][3] - mn1);
            rs0 += p00 + p01;
            rs1 += p10 + p11;
            // store P (as tf32) into warp-private smem in C-frag positions
            uint32_t* d0 = sp + g * PSTRIDE + nb * 8 + 2 * tg;
            uint32_t* d1 = sp + (g + 8) * PSTRIDE + nb * 8 + 2 * tg;
            d0[0] = f2tf(p00); d0[1] = f2tf(p01);
            d1[0] = f2tf(p10); d1[1] = f2tf(p11);
        }
        rs0 += __shfl_xor_sync(0xffffffffu, rs0, 1);
        rs0 += __shfl_xor_sync(0xffffffffu, rs0, 2);
        rs1 += __shfl_xor_sync(0xffffffffu, rs1, 1);
        rs1 += __shfl_xor_sync(0xffffffffu, rs1, 2);

        l0 = l0 * al0 + rs0;
        l1 = l1 * al1 + rs1;

#pragma unroll
        for (int nb = 0; nb < 16; nb++) {
            oacc[nb][0] *= al0; oacc[nb][1] *= al0;
            oacc[nb][2] *= al1; oacc[nb][3] *= al1;
        }

        __syncwarp();   // P stores visible to all lanes of this warp

        // ---- O += P * V  (k = 64 keys, n = 128 head dims) ----
#pragma unroll
        for (int kk = 0; kk < 8; kk++) {
            uint32_t ap[4];
            ap[0] = sp[g * PSTRIDE + kk * 8 + tg];
            ap[1] = sp[(g + 8) * PSTRIDE + kk * 8 + tg];
            ap[2] = sp[g * PSTRIDE + kk * 8 + tg + 4];
            ap[3] = sp[(g + 8) * PSTRIDE + kk * 8 + tg + 4];
#pragma unroll
            for (int nb = 0; nb < 16; nb++) {
                uint32_t b0 = sv[(kk * 8 + tg) * VSTRIDE + nb * 8 + g];
                uint32_t b1 = sv[(kk * 8 + tg + 4) * VSTRIDE + nb * 8 + g];
                mma_tf32(oacc[nb], ap, b0, b1);
            }
        }
    }

    // ---- Epilogue: normalize and store ----
    float inv0 = 1.f / l0, inv1 = 1.f / l1;
    const int r0 = qt0 + warp * 16 + g;
    float* o0 = O + base + (size_t)r0 * DHEAD;
    float* o1 = o0 + 8 * DHEAD;
#pragma unroll
    for (int nb = 0; nb < 16; nb++) {
        int c = nb * 8 + 2 * tg;
        float2 v0 = make_float2(oacc[nb][0] * inv0, oacc[nb][1] * inv0);
        float2 v1 = make_float2(oacc[nb][2] * inv1, oacc[nb][3] * inv1);
        *(float2*)(o0 + c) = v0;
        *(float2*)(o1 + c) = v1;
    }
}

extern "C" void kernel_launch(void* const* d_in, const int* in_sizes, int n_in,
                              void* d_out, int out_size) {
    const float* q = (const float*)d_in[0];
    const float* k = (const float*)d_in[1];
    const float* v = (const float*)d_in[2];
    float* o = (float*)d_out;

    cudaFuncSetAttribute(swa_kernel, cudaFuncAttributeMaxDynamicSharedMemorySize,
                         SMEM_BYTES);

    dim3 grid(L_SEQ / QTILE, 32);   // 64 q-tiles x (B*H)
    swa_kernel<<<grid, 128, SMEM_BYTES>>>(q, k, v, o);
}